// round 2
// baseline (speedup 1.0000x reference)
#include <cuda_runtime.h>
#include <cuda_bf16.h>

// Patch2Im (col2im / fold) gather kernel.
// x_patch: [B=4, C=64, k=7, k=7, nH=85, nW=85] float32
// fold with stride 3 -> [B, C, 259, 259], divide by counts, crop pad 3 -> [B, C, 253, 253]
//
// Gather formulation: out(y,x) = mean over patches covering (y,x).
// For y = h + 3 (uncropped coord), nh in [max(0, ceil((y-6)/3)), min(84, y/3)]  (<=3 values)
// i = y - 3*nh.  Same for x/nw/j. counts = cnt_h * cnt_w computed in registers.

#define NH 85
#define NW 85
#define KP 7
#define HOUT 253
#define WOUT 253
#define SPATIAL (HOUT * WOUT)   // 64009

__global__ __launch_bounds__(256) void patch2im_kernel(
    const float* __restrict__ in, float* __restrict__ out)
{
    const int spatial = blockIdx.x * 256 + threadIdx.x;
    if (spatial >= SPATIAL) return;
    const int bc = blockIdx.y;                 // 0..255  (b*64 + c)

    const int h = spatial / WOUT;
    const int w = spatial - h * WOUT;
    const int y = h + 3;                       // 3..255
    const int x = w + 3;

    // nh range (trunc division is fine: y>=3 so (y-4) >= -1, -1/3 == 0)
    int nh_lo = (y - 4) / 3; if (nh_lo < 0) nh_lo = 0;
    int nh_hi = y / 3;       if (nh_hi > NH - 1) nh_hi = NH - 1;
    int nw_lo = (x - 4) / 3; if (nw_lo < 0) nw_lo = 0;
    int nw_hi = x / 3;       if (nw_hi > NW - 1) nw_hi = NW - 1;

    const float* __restrict__ p = in + (size_t)bc * (KP * KP * NH * NW);

    float s = 0.0f;
    #pragma unroll 3
    for (int nh = nh_lo; nh <= nh_hi; ++nh) {
        const int i = y - 3 * nh;              // 0..6
        #pragma unroll 3
        for (int nw = nw_lo; nw <= nw_hi; ++nw) {
            const int j = x - 3 * nw;          // 0..6
            const int idx = ((i * KP + j) * NH + nh) * NW + nw;
            s += __ldg(p + idx);
        }
    }

    const int cnt = (nh_hi - nh_lo + 1) * (nw_hi - nw_lo + 1);
    out[(size_t)bc * SPATIAL + spatial] = s * (1.0f / (float)cnt);
}

extern "C" void kernel_launch(void* const* d_in, const int* in_sizes, int n_in,
                              void* d_out, int out_size)
{
    const float* in = (const float*)d_in[0];
    float* out = (float*)d_out;
    dim3 grid((SPATIAL + 255) / 256, 256);   // (251, 256)
    patch2im_kernel<<<grid, 256>>>(in, out);
}

// round 4
// speedup vs baseline: 3.8218x; 3.8218x over previous
#include <cuda_runtime.h>
#include <cuda_bf16.h>

// Patch2Im (col2im / fold), residue-specialized gather.
// in : [256 (b*c), 7 (i), 7 (j), 85 (nh), 85 (nw)] f32
// out: [256, 253, 253] f32
//
// Uncropped coord y = h + 3. Contributions: i ≡ y (mod 3), i in [0,6] =>
//   slot0: i = ry,   nh = my      (valid iff my <= 84)
//   slot1: i = ry+3, nh = my-1    (always valid)
//   slot2: i = ry+6, nh = my-2    (valid iff ry==0 && my >= 2)
// where ry = y%3 = h%3, my = y/3 = h/3 + 1. Same structure in x/w/j/nw.
// count = (#valid row slots) * (#valid col slots).

#define NHW 85
#define PLANE (NHW * NHW)        // 7225
#define CPLANE (49 * PLANE)      // 353975 floats per (b,c) plane
#define WOUT 253
#define HOUT 253
#define SPATIAL (WOUT * HOUT)

__global__ __launch_bounds__(256) void patch2im_kernel(
    const float* __restrict__ in, float* __restrict__ out)
{
    const int w = threadIdx.x;
    const int h = blockIdx.x;       // 0..252
    const int bc = blockIdx.y;      // 0..127 -> planes bc and bc+128

    // ---- row-uniform data (block-uniform -> uniform regs) ----
    const int ry = h % 3;
    const int my = h / 3 + 1;                  // 1..85
    const bool prA = (my <= 84);
    const bool prC = (ry == 0) && (my >= 2);
    const int row0 = (ry * 7) * PLANE + my * NHW;
    const int row1 = ((ry + 3) * 7) * PLANE + (my - 1) * NHW;
    const int row2 = ((ry + 6) * 7) * PLANE + (my - 2) * NHW;   // used iff prC

    if (w >= WOUT) return;

    // ---- per-thread column data ----
    const int rx = w % 3;
    const int m = w / 3 + 1;                   // 1..85
    const bool pcA = (m <= 84);
    const bool pcC = (rx == 0) && (m >= 2);
    const int colA = rx * PLANE + m;
    const int colB = (rx + 3) * PLANE + (m - 1);
    const int colC = (rx + 6) * PLANE + (m - 2);  // used iff pcC

    const float* __restrict__ p0 = in + (size_t)bc * CPLANE;
    const float* __restrict__ p1 = p0 + (size_t)128 * CPLANE;

    // ---- 9 predicated loads x 2 planes (all independent -> MLP 18) ----
    float a0 = 0.f, a1 = 0.f, a2 = 0.f, a3 = 0.f, a4 = 0.f,
          a5 = 0.f, a6 = 0.f, a7 = 0.f, a8 = 0.f;
    float b0 = 0.f, b1 = 0.f, b2 = 0.f, b3 = 0.f, b4 = 0.f,
          b5 = 0.f, b6 = 0.f, b7 = 0.f, b8 = 0.f;

    if (prA && pcA) { int o = row0 + colA; a0 = __ldg(p0 + o); b0 = __ldg(p1 + o); }
    if (prA)        { int o = row0 + colB; a1 = __ldg(p0 + o); b1 = __ldg(p1 + o); }
    if (prA && pcC) { int o = row0 + colC; a2 = __ldg(p0 + o); b2 = __ldg(p1 + o); }
    if (pcA)        { int o = row1 + colA; a3 = __ldg(p0 + o); b3 = __ldg(p1 + o); }
    {               int o = row1 + colB; a4 = __ldg(p0 + o); b4 = __ldg(p1 + o); }
    if (pcC)        { int o = row1 + colC; a5 = __ldg(p0 + o); b5 = __ldg(p1 + o); }
    if (prC && pcA) { int o = row2 + colA; a6 = __ldg(p0 + o); b6 = __ldg(p1 + o); }
    if (prC)        { int o = row2 + colB; a7 = __ldg(p0 + o); b7 = __ldg(p1 + o); }
    if (prC && pcC) { int o = row2 + colC; a8 = __ldg(p0 + o); b8 = __ldg(p1 + o); }

    const int cnt = (1 + (int)prA + (int)prC) * (1 + (int)pcA + (int)pcC);
    const float inv = 1.0f / (float)cnt;

    const float s0 = ((a0 + a1) + (a2 + a3)) + ((a4 + a5) + (a6 + a7)) + a8;
    const float s1 = ((b0 + b1) + (b2 + b3)) + ((b4 + b5) + (b6 + b7)) + b8;

    const size_t obase = (size_t)bc * SPATIAL + (size_t)h * WOUT + w;
    out[obase] = s0 * inv;
    out[obase + (size_t)128 * SPATIAL] = s1 * inv;
}

extern "C" void kernel_launch(void* const* d_in, const int* in_sizes, int n_in,
                              void* d_out, int out_size)
{
    const float* in = (const float*)d_in[0];
    float* out = (float*)d_out;
    dim3 grid(HOUT, 128);   // (253 rows, 128 bc-pairs)
    patch2im_kernel<<<grid, 256>>>(in, out);
}